// round 2
// baseline (speedup 1.0000x reference)
#include <cuda_runtime.h>
#include <cstdint>

// CTC loss forward — faithful log-domain port of tf.keras ctc_batch_cost.
// One warp per batch element. State layout (S = 129 = 2*64+1), lane l:
//   A0 = alpha[2l]      (blank, even)
//   A1 = alpha[2l+1]    (label lab[l], odd)
//   A2 = alpha[64+2l]   (blank, even)
//   A3 = alpha[65+2l]   (label lab[32+l], odd)
//   A4 = alpha[128]     (blank; only lane 0's value is meaningful)
//
// Semantics match the reference exactly: logaddexp recursion, NEG=-1e30,
// log(y_pred + 1e-7) emissions. Validity masks are omitted: CTC transitions
// are non-decreasing in s, so states s >= 2L+1 never influence states
// s <= 2L, and the final readout only touches s = 2L, 2L-1.
// Even (blank) states have no skip transition -> only 4 shuffles per step.

#define WARP_FULL 0xffffffffu
#define RCHUNK 8
#define NEGV  (-1e30f)
#define EPSV  (1e-7f)

__device__ __forceinline__ float lae2(float a, float b) {
    float m = fmaxf(a, b);
    float d = fminf(a, b) - m;               // <= 0
    return m + __logf(1.0f + __expf(d));
}

__device__ __forceinline__ float lae3(float a, float b, float c) {
    float m = fmaxf(fmaxf(a, b), c);
    float x = __expf(a - m) + __expf(b - m) + __expf(c - m);
    return m + __logf(x);
}

__global__ __launch_bounds__(32, 1)
void ctc_fwd_log_kernel(const int* __restrict__ y_true,
                        const float* __restrict__ y_pred,
                        const int* __restrict__ input_len,
                        const int* __restrict__ label_len,
                        float* __restrict__ out,
                        int T, int C, int Lmax)
{
    const int b = blockIdx.x;
    const int l = threadIdx.x;

    const float* P  = y_pred + (size_t)b * T * C;
    const int*  lab = y_true + (size_t)b * Lmax;

    int L = label_len[b];
    if (L > Lmax) L = Lmax;
    int Tlen = input_len[b];
    int tEnd = Tlen < 1 ? 1 : (Tlen > T ? T : Tlen);

    const int blank = C - 1;

    // per-lane label classes and skip-allowed flags
    const int c1  = lab[l];                 // state 2l+1
    const int c3  = lab[32 + l];            // state 65+2l
    const int c3m = lab[31 + l];
    const int c1m = (l >= 1) ? lab[l - 1] : -1;
    const bool skip1 = (l >= 1) && (c1 != c1m);
    const bool skip3 = (c3 != c3m);

    // ---- t = 0 init ----
    float A0 = (l == 0)          ? __logf(__ldg(P + blank) + EPSV) : NEGV;
    float A1 = (l == 0 && L > 0) ? __logf(__ldg(P + c1)    + EPSV) : NEGV;
    float A2 = NEGV, A3 = NEGV, A4 = NEGV;

    // ---- prefetch chunk t = 1..RCHUNK ----
    float pb[RCHUNK], p1[RCHUNK], p3[RCHUNK];
    #pragma unroll
    for (int j = 0; j < RCHUNK; j++) {
        int t = 1 + j;
        const float* row = P + (size_t)(t < T ? t : T - 1) * C;
        pb[j] = __ldg(row + blank);
        p1[j] = __ldg(row + c1);
        p3[j] = __ldg(row + c3);
    }

    for (int tb = 1; tb < tEnd; tb += RCHUNK) {
        // prefetch next chunk while computing this one
        float nb[RCHUNK], n1[RCHUNK], n3[RCHUNK];
        #pragma unroll
        for (int j = 0; j < RCHUNK; j++) {
            int t = tb + RCHUNK + j;
            const float* row = P + (size_t)(t < T ? t : T - 1) * C;
            nb[j] = __ldg(row + blank);
            n1[j] = __ldg(row + c1);
            n3[j] = __ldg(row + c3);
        }

        #pragma unroll
        for (int j = 0; j < RCHUNK; j++) {
            int t = tb + j;
            if (t >= tEnd) break;

            float eb = __logf(pb[j] + EPSV);
            float e1 = __logf(p1[j] + EPSV);
            float e3 = __logf(p3[j] + EPSV);

            float u1  = __shfl_up_sync(WARP_FULL, A1, 1);   // alpha[2l-1]
            float u3  = __shfl_up_sync(WARP_FULL, A3, 1);   // alpha[63+2l], l>=1
            float bA1 = __shfl_sync(WARP_FULL, A1, 31);     // alpha[63]
            float bA3 = __shfl_sync(WARP_FULL, A3, 31);     // alpha[127]

            float u1z = (l == 0) ? NEGV : u1;               // pred of s=2l
            float q   = (l == 0) ? bA1  : u3;               // alpha[63+2l]
            float s1  = skip1 ? u1 : NEGV;
            float s3  = skip3 ? q  : NEGV;

            float n0v = lae2(A0, u1z)    + eb;              // s=2l
            float n1v = lae3(A1, A0, s1) + e1;              // s=2l+1
            float n2v = lae2(A2, q)      + eb;              // s=64+2l
            float n3v = lae3(A3, A2, s3) + e3;              // s=65+2l
            float n4v = lae2(A4, bA3)    + eb;              // s=128

            A0 = n0v; A1 = n1v; A2 = n2v; A3 = n3v; A4 = n4v;
        }

        #pragma unroll
        for (int j = 0; j < RCHUNK; j++) { pb[j] = nb[j]; p1[j] = n1[j]; p3[j] = n3[j]; }
    }

    // ---- final: ll = logaddexp(alpha[2L], alpha[2L-1]) ----
    __shared__ float sA[129];
    sA[2 * l]      = A0;
    sA[2 * l + 1]  = A1;
    sA[64 + 2 * l] = A2;
    sA[65 + 2 * l] = A3;
    if (l == 0) sA[128] = A4;
    __syncwarp();

    if (l == 0) {
        float a_last = sA[2 * L];
        float a_prev = (L > 0) ? sA[2 * L - 1] : NEGV;
        float ll = lae2(a_last, a_prev);
        out[b] = -ll;
    }
}

extern "C" void kernel_launch(void* const* d_in, const int* in_sizes, int n_in,
                              void* d_out, int out_size)
{
    const int*   y_true    = (const int*)  d_in[0];
    const float* y_pred    = (const float*)d_in[1];
    const int*   input_len = (const int*)  d_in[2];
    const int*   label_len = (const int*)  d_in[3];
    float* out = (float*)d_out;

    int B = out_size;                    // out is [B,1]
    int Lmax = in_sizes[0] / B;          // 64
    int C = 256;
    int T = in_sizes[1] / (B * C);       // 1024

    ctc_fwd_log_kernel<<<B, 32>>>(y_true, y_pred, input_len, label_len, out, T, C, Lmax);
}